// round 17
// baseline (speedup 1.0000x reference)
#include <cuda_runtime.h>
#include <cuda_fp16.h>
#include <cuda_bf16.h>
#include <cstdint>

#define NUM_NETS_MAX 2000000

// Per-net accumulators packed as 2x f16x2 in 8 bytes:
//   .x = half2{exp(+x/g), exp(-x/g)}, .y = half2{exp(+y/g), exp(-y/g)}
// Zero at module load; nets kernel re-zeroes after consuming each slot so
// every launch / graph replay starts from zeros.
__device__ uint2 g_net_sums_h[NUM_NETS_MAX];

// ---------------------------------------------------------------------------
// Pins: per-pin exp + scatter-add. 8 pins per thread; all 6 wide loads
// batched up front; __ldcs keeps the 120MB stream from displacing the 16MB
// L2-resident scratch. ONE red.global.add.noftz.v2.f16x2 (8B) per pin.
// Handles the (num_pins % 8) tail inline from the last thread.
// ---------------------------------------------------------------------------
__device__ __forceinline__ void scatter_pin(float sx, float sy, int net) {
    float epx = __expf(sx);
    float enx = __expf(-sx);
    float epy = __expf(sy);
    float eny = __expf(-sy);
    __half2 hx = __floats2half2_rn(epx, enx);
    __half2 hy = __floats2half2_rn(epy, eny);
    unsigned rx = *reinterpret_cast<unsigned*>(&hx);
    unsigned ry = *reinterpret_cast<unsigned*>(&hy);
    asm volatile("red.global.add.noftz.v2.f16x2 [%0], {%1, %2};"
                 :: "l"(&g_net_sums_h[net]), "r"(rx), "r"(ry)
                 : "memory");
}

__global__ void __launch_bounds__(256) pins_kernel_vec8(
    const float4* __restrict__ posx,
    const float4* __restrict__ posy,
    const int4*   __restrict__ pin2net,
    const float*  __restrict__ gamma_ptr,
    float* __restrict__ out,
    int num_octs,     // num_pins / 8
    int num_pins)
{
    int t = blockIdx.x * blockDim.x + threadIdx.x;
    if (t == 0) *out = 0.f;   // nets kernel (later in stream) accumulates into it

    float inv_g = 1.0f / (*gamma_ptr);

    if (t < num_octs) {
        int q0 = 2 * t;
        int q1 = 2 * t + 1;

        // batch all 6 wide loads before any use; evict-first (streaming)
        float4 px0 = __ldcs(&posx[q0]);
        float4 px1 = __ldcs(&posx[q1]);
        float4 py0 = __ldcs(&posy[q0]);
        float4 py1 = __ldcs(&posy[q1]);
        int4   n0  = __ldcs(&pin2net[q0]);
        int4   n1  = __ldcs(&pin2net[q1]);

        scatter_pin(px0.x * inv_g, py0.x * inv_g, n0.x);
        scatter_pin(px0.y * inv_g, py0.y * inv_g, n0.y);
        scatter_pin(px0.z * inv_g, py0.z * inv_g, n0.z);
        scatter_pin(px0.w * inv_g, py0.w * inv_g, n0.w);
        scatter_pin(px1.x * inv_g, py1.x * inv_g, n1.x);
        scatter_pin(px1.y * inv_g, py1.y * inv_g, n1.y);
        scatter_pin(px1.z * inv_g, py1.z * inv_g, n1.z);
        scatter_pin(px1.w * inv_g, py1.w * inv_g, n1.w);
    } else if (t == num_octs) {
        // tail pins (num_pins % 8), handled by one extra thread
        const float* fx = reinterpret_cast<const float*>(posx);
        const float* fy = reinterpret_cast<const float*>(posy);
        const int*   nn = reinterpret_cast<const int*>(pin2net);
        for (int p = num_octs * 8; p < num_pins; p++)
            scatter_pin(__ldcs(&fx[p]) * inv_g, __ldcs(&fy[p]) * inv_g,
                        __ldcs(&nn[p]));
    }
}

// ---------------------------------------------------------------------------
// Nets: grid-stride streaming reducer, 8 nets per iteration. ALL 6 loads
// batched before uses/stores (MLP). log(a)+log(b)+log(c)+log(d) =
// log(a*b*c*d); the four sums of a net are zero together (same pin set), so
// one prod>0 guard handles empty nets exactly. net_mask is int32 on device.
// ---------------------------------------------------------------------------
__device__ __forceinline__ float net_term(unsigned rawx, unsigned rawy) {
    __half2 hx = *reinterpret_cast<__half2*>(&rawx);
    __half2 hy = *reinterpret_cast<__half2*>(&rawy);
    float spx = __low2float(hx);
    float snx = __high2float(hx);
    float spy = __low2float(hy);
    float sny = __high2float(hy);
    float prod = (spx * snx) * (spy * sny);
    return (prod > 0.f) ? __logf(prod) : 0.f;
}

__global__ void __launch_bounds__(256) nets_kernel_gs8(
    const int4*  __restrict__ mask4,
    const float* __restrict__ gamma_ptr,
    float* __restrict__ out,
    int num_octs,        // num_nets / 8
    int tail_start,      // num_octs * 8
    int num_nets)
{
    uint4* sums4 = reinterpret_cast<uint4*>(g_net_sums_h);  // 2 nets per uint4
    const uint4 z4 = make_uint4(0u, 0u, 0u, 0u);

    int tid    = blockIdx.x * blockDim.x + threadIdx.x;
    int stride = gridDim.x * blockDim.x;

    float v = 0.f;

    for (int i = tid; i < num_octs; i += stride) {
        // ALL 6 loads batched before any use or store (max MLP)
        uint4 s0 = sums4[4 * i];        // nets 8i+0, 8i+1
        uint4 s1 = sums4[4 * i + 1];    // nets 8i+2, 8i+3
        uint4 s2 = sums4[4 * i + 2];    // nets 8i+4, 8i+5
        uint4 s3 = sums4[4 * i + 3];    // nets 8i+6, 8i+7
        int4  m0 = __ldcs(&mask4[2 * i]);
        int4  m1 = __ldcs(&mask4[2 * i + 1]);

        if (m0.x) v += net_term(s0.x, s0.y);
        if (m0.y) v += net_term(s0.z, s0.w);
        if (m0.z) v += net_term(s1.x, s1.y);
        if (m0.w) v += net_term(s1.z, s1.w);
        if (m1.x) v += net_term(s2.x, s2.y);
        if (m1.y) v += net_term(s2.z, s2.w);
        if (m1.z) v += net_term(s3.x, s3.y);
        if (m1.w) v += net_term(s3.z, s3.w);

        sums4[4 * i]     = z4;          // reset for next launch
        sums4[4 * i + 1] = z4;
        sums4[4 * i + 2] = z4;
        sums4[4 * i + 3] = z4;
    }

    // scalar tail (num_nets % 8)
    const int* mask1 = reinterpret_cast<const int*>(mask4);
    for (int n = tail_start + tid; n < num_nets; n += stride) {
        uint2 raw = g_net_sums_h[n];
        g_net_sums_h[n] = make_uint2(0u, 0u);
        if (mask1[n]) v += net_term(raw.x, raw.y);
    }

    // block reduce (once per block)
    #pragma unroll
    for (int o = 16; o > 0; o >>= 1)
        v += __shfl_down_sync(0xFFFFFFFFu, v, o);

    __shared__ float sh[8];
    int lane = threadIdx.x & 31;
    int wid  = threadIdx.x >> 5;
    if (lane == 0) sh[wid] = v;
    __syncthreads();

    if (wid == 0) {
        float bv = (lane < 8) ? sh[lane] : 0.f;
        #pragma unroll
        for (int o = 4; o > 0; o >>= 1)
            bv += __shfl_down_sync(0xFFFFFFFFu, bv, o);
        if (lane == 0)
            atomicAdd(out, (*gamma_ptr) * bv);
    }
}

// ---------------------------------------------------------------------------
extern "C" void kernel_launch(void* const* d_in, const int* in_sizes, int n_in,
                              void* d_out, int out_size)
{
    const float* pos       = (const float*)d_in[0];   // [2 * num_pins]
    const int*   pin2net   = (const int*)d_in[1];     // [num_pins]
    const int*   net_mask  = (const int*)d_in[2];     // [num_nets] (bool as i32)
    const float* gamma_ptr = (const float*)d_in[3];   // scalar

    int num_pins = in_sizes[0] / 2;
    int num_nets = in_sizes[2];
    float* out = (float*)d_out;

    const int T = 256;

    // Two launches total: pins (includes out=0 and tail), then nets.
    int num_pin_octs = num_pins / 8;
    int pthreads = num_pin_octs + 1;           // +1 thread for the tail
    int pb = (pthreads + T - 1) / T;
    pins_kernel_vec8<<<pb, T>>>(
        (const float4*)pos, (const float4*)(pos + num_pins),
        (const int4*)pin2net, gamma_ptr, out, num_pin_octs, num_pins);

    int num_net_octs = num_nets / 8;
    int tail_start_n = num_net_octs * 8;
    // 7 blocks/SM (regs=36 -> 7 resident at 256T) x 148 SMs = single full wave
    int nblocks = 1036;
    nets_kernel_gs8<<<nblocks, T>>>(
        (const int4*)net_mask, gamma_ptr, out,
        num_net_octs, tail_start_n, num_nets);
}